// round 5
// baseline (speedup 1.0000x reference)
#include <cuda_runtime.h>
#include <math.h>

#define EMB   64
#define NS    25
#define DEG   64
#define BATCH 4096
#define GRIDP 148              // persistent blocks, 1/SM
#define NBUF  4                // feat ring slots (power of 2)

typedef unsigned long long ull;

// fma.rn.f32x2 — packed fp32 FMA (Blackwell). acc += a*b (two lanes)
#define FFMA2(acc, a, b) \
    asm("fma.rn.f32x2 %0, %1, %2, %3;" : "=l"(acc) : "l"(a), "l"(b), "l"(acc))

// A layout: [64 colgroups][16 k4][4 cols][4 k], group stride 260 floats
#define A_GS 260
#define A_FLOATS (64 * A_GS)    // 16640

// ---------------- static device scratch (no allocation) --------------------
__device__ float g_At[A_FLOATS];              // folded layer-1 weights, blocked
__device__ float g_bias1[256];                // [b1x ; b1n]
__device__ float g_x0[128];                   // feats0 @ w1x.T (pre-relu)
__device__ float g_W2t[512 * 256];            // layer-2 weights [128 kp][256 c][2]
__device__ float g_scr[(size_t)BATCH * 512];  // per batch: [h0cat(256) | h1mean(256)]

// ---------------------------------------------------------------------------
__global__ void prep_A(const float* __restrict__ prep_W,
                       const float* __restrict__ w1x,
                       const float* __restrict__ w1n) {
    int idx = blockIdx.x * 128 + threadIdx.x;   // 0..8191
    int k = idx >> 7, h = idx & 127;
    float ax = 0.f, an = 0.f;
#pragma unroll
    for (int c = 0; c < 64; c++) {
        float p = prep_W[c * 64 + k];
        ax += p * w1x[h * 64 + c];
        an += p * w1n[h * 64 + c];
    }
    int cx = h, cn = 128 + h;
    g_At[(cx >> 2) * A_GS + (k >> 2) * 16 + (cx & 3) * 4 + (k & 3)] = ax;
    g_At[(cn >> 2) * A_GS + (k >> 2) * 16 + (cn & 3) * 4 + (k & 3)] = an;
}

// ---------------------------------------------------------------------------
__global__ void prep_B(const float* __restrict__ emb,
                       const float* __restrict__ prep_W,
                       const float* __restrict__ prep_b,
                       const float* __restrict__ w1x,
                       const float* __restrict__ w1n,
                       int n_nodes) {
    __shared__ float f0[64];
    int t = threadIdx.x;
    if (t < 64) {
        const float* e = emb + (size_t)n_nodes * 64;
        float a = prep_b[t];
#pragma unroll
        for (int k = 0; k < 64; k++) a += e[k] * prep_W[t * 64 + k];
        f0[t] = a;
    }
    __syncthreads();
    float x0 = 0.f, bx = 0.f, bn = 0.f;
#pragma unroll
    for (int c = 0; c < 64; c++) {
        x0 += f0[c]     * w1x[t * 64 + c];
        bx += prep_b[c] * w1x[t * 64 + c];
        bn += prep_b[c] * w1n[t * 64 + c];
    }
    g_x0[t]          = x0;
    g_bias1[t]       = bx;
    g_bias1[128 + t] = bn;
}

// ---------------------------------------------------------------------------
// prep_W2: transpose/pack layer-2 weights for coalesced FFMA2 access.
// g_W2t[kp*512 + c*2 + e] = W_c[2*kp + e]
// ---------------------------------------------------------------------------
__global__ void prep_W2(const float* __restrict__ w2x,
                        const float* __restrict__ w2n) {
    int idx = blockIdx.x * 256 + threadIdx.x;   // 0..131071
    int c = idx & 255, kk = idx >> 8;           // kk 0..511
    float v = (c < 128) ? w2x[c * 256 + kk] : w2n[(c - 128) * 256 + kk];
    g_W2t[(kk >> 1) * 512 + c * 2 + (kk & 1)] = v;
}

// ---------------------------------------------------------------------------
// fused_ws: persistent warp-specialized kernel.
// Warps 8-15 (threads 256-511): producers — gather [e1|mean2] for 25 samples
//   of batch i into ring slot (it & 3). Stage-batched loads for short chains.
// Warps 0-7 (threads 0-255): consumers — layer-1 GEMM + relu-mean + epilogue.
// Sync: shared sequence flags (sFull/sEmpty) + named barriers 1/2.
// smem floats: A 16640 | ring 4x3200 | H1 256 | mean 64 | bias 256 | flags
// ---------------------------------------------------------------------------
#define SMO_F   A_FLOATS                        // 16640
#define SMO_H1  (SMO_F + NBUF * NS * 128)       // 29440
#define SMO_MN  (SMO_H1 + 256)                  // 29696
#define SMO_B   (SMO_MN + 64)                   // 29760
#define SMO_FLG (SMO_B + 256)                   // 30016
#define SM_FLOATS (SMO_FLG + 2 * NBUF)          // 30024

__global__ void __launch_bounds__(512, 1)
fused_ws(const float* __restrict__ emb,
         const int* __restrict__ ids,
         const int* __restrict__ adj,
         const int* __restrict__ perm1,
         const int* __restrict__ perm2) {
    extern __shared__ float sm[];
    float* sA    = sm;
    float* sH1   = sm + SMO_H1;
    float* sMean = sm + SMO_MN;
    float* sBias = sm + SMO_B;
    volatile int* sFull  = (volatile int*)(sm + SMO_FLG);
    volatile int* sEmpty = sFull + NBUF;

    const int t = threadIdx.x;
    const float inv25 = 1.0f / 25.0f;

    // stage A + init (all 512 threads)
    {
        const float4* src = (const float4*)g_At;
        float4* dst = (float4*)sA;
        for (int idx = t; idx < A_FLOATS / 4; idx += 512) dst[idx] = src[idx];
        if (t < 256) { sBias[t] = g_bias1[t]; sH1[t] = 0.f; }
        if (t < NBUF) { ((int*)sFull)[t] = -1; ((int*)sEmpty)[t] = -1; }
    }
    __syncthreads();

    const int bk = blockIdx.x;
    const int nIter = (BATCH - bk + GRIDP - 1) / GRIDP;

    if (t >= 256) {
        // ======================= PRODUCERS =======================
        const int pt = t - 256;
        const int pw = pt >> 5, lane = pt & 31;
        const int p2 = __ldg(&perm2[lane < NS ? lane : 0]);
        const int nj = (pw == 0) ? 4 : 3;      // samples: j = pw + 8*m

        for (int it = 0; it < nIter; it++) {
            const int i = bk + it * GRIDP;
            const int slot = it & (NBUF - 1);
            while (sEmpty[slot] < it - NBUF) { }
            float* sF = sm + SMO_F + slot * (NS * 128);
            const int id0 = __ldg(&ids[i]);

            int id1s[4], nbs[4];
            float2 e1s[4];
#pragma unroll
            for (int m = 0; m < 4; m++)
                if (m < nj)
                    id1s[m] = __ldg(&adj[(size_t)id0 * DEG + __ldg(&perm1[pw + 8 * m])]);
#pragma unroll
            for (int m = 0; m < 4; m++)
                if (m < nj) nbs[m] = __ldg(&adj[(size_t)id1s[m] * DEG + p2]);
#pragma unroll
            for (int m = 0; m < 4; m++)
                if (m < nj) e1s[m] = *(const float2*)(emb + (size_t)id1s[m] * 64 + 2 * lane);

            float sx[4] = {0, 0, 0, 0}, sy[4] = {0, 0, 0, 0};
#pragma unroll
            for (int k = 0; k < NS; k++) {
#pragma unroll
                for (int m = 0; m < 4; m++) {
                    if (m < nj) {
                        int idk = __shfl_sync(0xffffffffu, nbs[m], k);
                        float2 v = *(const float2*)(emb + (size_t)idk * 64 + 2 * lane);
                        sx[m] += v.x; sy[m] += v.y;
                    }
                }
            }
#pragma unroll
            for (int m = 0; m < 4; m++) {
                if (m < nj) {
                    int j = pw + 8 * m;
                    *(float2*)(sF + j * 128 + 2 * lane) = e1s[m];
                    *(float2*)(sF + j * 128 + 64 + 2 * lane)
                        = make_float2(sx[m] * inv25, sy[m] * inv25);
                }
            }
            asm volatile("bar.sync 1, 256;" ::: "memory");  // producer warps; drains STS
            if (pt == 0) sFull[slot] = it;
        }
    } else {
        // ======================= CONSUMERS =======================
        const int cg = t & 63;                 // column group -> cols c0..c0+3
        const int sg = t >> 6;                 // sample subset: s = sg + 4m
        const int c0 = cg * 4;
        const int kbase = (cg < 32) ? 0 : 64;  // e1-part vs mean2-part
        const float* Ab = sA + cg * A_GS;
        const float x0r = (t < 128) ? g_x0[t] : 0.f;

        for (int it = 0; it < nIter; it++) {
            const int i = bk + it * GRIDP;
            const int slot = it & (NBUF - 1);
            while (sFull[slot] < it) { }
            const float* sF = sm + SMO_F + slot * (NS * 128);
            const float* fb = sF + kbase;

            ull acc[7][4];
#pragma unroll
            for (int m = 0; m < 7; m++)
#pragma unroll
                for (int j = 0; j < 4; j++) acc[m][j] = 0ull;

#pragma unroll
            for (int k4 = 0; k4 < 16; k4++) {
                ulonglong2 a0 = *(const ulonglong2*)(Ab + k4 * 16);
                ulonglong2 a1 = *(const ulonglong2*)(Ab + k4 * 16 + 4);
                ulonglong2 a2 = *(const ulonglong2*)(Ab + k4 * 16 + 8);
                ulonglong2 a3 = *(const ulonglong2*)(Ab + k4 * 16 + 12);
#pragma unroll
                for (int m = 0; m < 7; m++) {
                    int s = sg + 4 * m;
                    if (s < NS) {
                        ulonglong2 f2 = *(const ulonglong2*)(fb + s * 128 + k4 * 4);
                        FFMA2(acc[m][0], f2.x, a0.x); FFMA2(acc[m][0], f2.y, a0.y);
                        FFMA2(acc[m][1], f2.x, a1.x); FFMA2(acc[m][1], f2.y, a1.y);
                        FFMA2(acc[m][2], f2.x, a2.x); FFMA2(acc[m][2], f2.y, a2.y);
                        FFMA2(acc[m][3], f2.x, a3.x); FFMA2(acc[m][3], f2.y, a3.y);
                    }
                }
            }

            float hs[4] = {0.f, 0.f, 0.f, 0.f};
#pragma unroll
            for (int m = 0; m < 7; m++) {
                int s = sg + 4 * m;
                if (s < NS) {
#pragma unroll
                    for (int j = 0; j < 4; j++) {
                        float lo = __uint_as_float((unsigned)acc[m][j]);
                        float hi = __uint_as_float((unsigned)(acc[m][j] >> 32));
                        hs[j] += fmaxf(lo + hi + sBias[c0 + j], 0.f);
                    }
                }
            }
#pragma unroll
            for (int j = 0; j < 4; j++) atomicAdd(&sH1[c0 + j], hs[j]);

            if (t < 64) {
                float m = 0.f;
#pragma unroll
                for (int s = 0; s < NS; s++) m += sF[s * 128 + t];
                sMean[t] = m * inv25;
            }
            asm volatile("bar.sync 2, 256;" ::: "memory");

            // epilogue -> g_scr
            float* scr = g_scr + (size_t)i * 512;
            if (t < 128) {
                scr[t] = fmaxf(x0r, 0.f);
            } else {
                int cgc = t >> 2, jc = t & 3;
                const float* Ac = sA + cgc * A_GS + jc * 4;
                float a = 0.f;
#pragma unroll
                for (int k4 = 0; k4 < 16; k4++) {
                    float4 av = *(const float4*)(Ac + k4 * 16);
                    float4 mv = *(const float4*)(sMean + k4 * 4);
                    a += av.x * mv.x + av.y * mv.y + av.z * mv.z + av.w * mv.w;
                }
                scr[t] = fmaxf(a + sBias[t], 0.f);
            }
            scr[256 + t] = sH1[t] * inv25;
            sH1[t] = 0.f;                       // owner reset
            asm volatile("bar.sync 2, 256;" ::: "memory");
            if (t == 0) sEmpty[slot] = it;
        }
    }
}

// ---------------------------------------------------------------------------
// final2: layer-2 GEMM with packed transposed weights. 32 rows/block,
// thread = 4 cols x 8 rows; then L2-normalize + fc.
// ---------------------------------------------------------------------------
__global__ void __launch_bounds__(256)
final2(const float* __restrict__ fcW,
       const float* __restrict__ fcb,
       float* __restrict__ out) {
    extern __shared__ float fsm[];
    float* in_sh = fsm;                 // 32 x 512
    float* sSq   = fsm + 32 * 512;      // 32
    float* sDot  = sSq + 32;            // 32

    int t  = threadIdx.x;
    int r0 = blockIdx.x * 32;

    {
        const float4* src = (const float4*)(g_scr + (size_t)r0 * 512);
        float4* dst = (float4*)in_sh;
#pragma unroll
        for (int q = 0; q < 16; q++) dst[t + q * 256] = src[t + q * 256];
    }
    if (t < 32) { sSq[t] = 0.f; sDot[t] = 0.f; }
    __syncthreads();

    const int c4 = (t & 63) * 4;            // 4 output cols
    const int rg = t >> 6;                  // row group (8 rows)
    const int ioff = (c4 < 128) ? 0 : 256;
    const float* xb = in_sh + rg * 8 * 512 + ioff;

    ull acc[8][4];
#pragma unroll
    for (int r = 0; r < 8; r++)
#pragma unroll
        for (int j = 0; j < 4; j++) acc[r][j] = 0ull;

#pragma unroll 4
    for (int kp = 0; kp < 128; kp++) {
        ulonglong2 wA = *(const ulonglong2*)(g_W2t + kp * 512 + c4 * 2);
        ulonglong2 wB = *(const ulonglong2*)(g_W2t + kp * 512 + c4 * 2 + 4);
#pragma unroll
        for (int r = 0; r < 8; r++) {
            ull x2 = *(const ull*)(xb + r * 512 + 2 * kp);
            FFMA2(acc[r][0], x2, wA.x);
            FFMA2(acc[r][1], x2, wA.y);
            FFMA2(acc[r][2], x2, wB.x);
            FFMA2(acc[r][3], x2, wB.y);
        }
    }

    float4 fw = *(const float4*)(fcW + c4);
    int lane = t & 31;
#pragma unroll
    for (int r = 0; r < 8; r++) {
        float v[4];
#pragma unroll
        for (int j = 0; j < 4; j++)
            v[j] = __uint_as_float((unsigned)acc[r][j])
                 + __uint_as_float((unsigned)(acc[r][j] >> 32));
        float sq = v[0]*v[0] + v[1]*v[1] + v[2]*v[2] + v[3]*v[3];
        float dt = v[0]*fw.x + v[1]*fw.y + v[2]*fw.z + v[3]*fw.w;
#pragma unroll
        for (int o = 16; o > 0; o >>= 1) {
            sq += __shfl_xor_sync(0xffffffffu, sq, o);
            dt += __shfl_xor_sync(0xffffffffu, dt, o);
        }
        if (lane == 0) {
            atomicAdd(&sSq[rg * 8 + r], sq);
            atomicAdd(&sDot[rg * 8 + r], dt);
        }
    }
    __syncthreads();
    if (t < 32) {
        float nrm = sqrtf(sSq[t]);
        out[r0 + t] = sDot[t] / fmaxf(nrm, 1e-12f) + fcb[0];
    }
}

// ---------------------------------------------------------------------------
extern "C" void kernel_launch(void* const* d_in, const int* in_sizes, int n_in,
                              void* d_out, int out_size) {
    const float* embedding = (const float*)d_in[0];
    const float* prep_W    = (const float*)d_in[1];
    const float* prep_b    = (const float*)d_in[2];
    const float* w1x       = (const float*)d_in[3];
    const float* w1n       = (const float*)d_in[4];
    const float* w2x       = (const float*)d_in[5];
    const float* w2n       = (const float*)d_in[6];
    const float* fcW       = (const float*)d_in[7];
    const float* fcb       = (const float*)d_in[8];
    const int*   ids       = (const int*)d_in[9];
    const int*   adj       = (const int*)d_in[10];
    const int*   perm1     = (const int*)d_in[11];
    const int*   perm2     = (const int*)d_in[12];
    const int n_nodes = in_sizes[0] / EMB - 1;

    prep_A<<<64, 128>>>(prep_W, w1x, w1n);
    prep_B<<<1, 128>>>(embedding, prep_W, prep_b, w1x, w1n, n_nodes);
    prep_W2<<<512, 256>>>(w2x, w2n);

    const int smem_f = SM_FLOATS * (int)sizeof(float);
    cudaFuncSetAttribute(fused_ws, cudaFuncAttributeMaxDynamicSharedMemorySize, smem_f);
    fused_ws<<<GRIDP, 512, smem_f>>>(embedding, ids, adj, perm1, perm2);

    const int smem_o = (32 * 512 + 64) * (int)sizeof(float);
    cudaFuncSetAttribute(final2, cudaFuncAttributeMaxDynamicSharedMemorySize, smem_o);
    final2<<<BATCH / 32, 256, smem_o>>>(fcW, fcb, (float*)d_out);
}

// round 6
// speedup vs baseline: 3.2447x; 3.2447x over previous
#include <cuda_runtime.h>
#include <math.h>

#define EMB   64
#define NS    25
#define DEG   64
#define BATCH 4096
#define CHUNK 1024                  // batches per pipeline chunk
#define NCHUNK (BATCH / CHUNK)      // 4
#define GBLK  (CHUNK * NS / 8)      // 3200 gather blocks per chunk (warp = 1 sample)
#define CBLK  (CHUNK / 2)           // 512 compute blocks per chunk (block = 2 batches)

typedef unsigned long long ull;

// fma.rn.f32x2 — packed fp32 FMA (Blackwell). acc += a*b (two lanes)
#define FFMA2(acc, a, b) \
    asm("fma.rn.f32x2 %0, %1, %2, %3;" : "=l"(acc) : "l"(a), "l"(b), "l"(acc))

// A layout: [64 colgroups][16 k4][4 cols][4 k], group stride 260 floats
#define A_GS 260
#define A_FLOATS (64 * A_GS)    // 16640

// ---------------- static device scratch (no allocation) --------------------
__device__ float g_At[A_FLOATS];              // folded layer-1 weights, blocked
__device__ float g_bias1[256];                // [b1x ; b1n]
__device__ float g_x0[128];                   // feats0 @ w1x.T (pre-relu)
__device__ float g_W2t[512 * 256];            // layer-2 weights [128 kp][256 c][2]
__device__ float g_feats[(size_t)BATCH * NS * 128]; // per sample: [e1(64)|mean2(64)]
__device__ float g_scr[(size_t)BATCH * 512];  // per batch: [h0cat(256) | h1mean(256)]

// ---------------------------------------------------------------------------
__global__ void prep_A(const float* __restrict__ prep_W,
                       const float* __restrict__ w1x,
                       const float* __restrict__ w1n) {
    int idx = blockIdx.x * 128 + threadIdx.x;   // 0..8191
    int k = idx >> 7, h = idx & 127;
    float ax = 0.f, an = 0.f;
#pragma unroll
    for (int c = 0; c < 64; c++) {
        float p = prep_W[c * 64 + k];
        ax += p * w1x[h * 64 + c];
        an += p * w1n[h * 64 + c];
    }
    int cx = h, cn = 128 + h;
    g_At[(cx >> 2) * A_GS + (k >> 2) * 16 + (cx & 3) * 4 + (k & 3)] = ax;
    g_At[(cn >> 2) * A_GS + (k >> 2) * 16 + (cn & 3) * 4 + (k & 3)] = an;
}

// ---------------------------------------------------------------------------
__global__ void prep_B(const float* __restrict__ emb,
                       const float* __restrict__ prep_W,
                       const float* __restrict__ prep_b,
                       const float* __restrict__ w1x,
                       const float* __restrict__ w1n,
                       int n_nodes) {
    __shared__ float f0[64];
    int t = threadIdx.x;
    if (t < 64) {
        const float* e = emb + (size_t)n_nodes * 64;
        float a = prep_b[t];
#pragma unroll
        for (int k = 0; k < 64; k++) a += e[k] * prep_W[t * 64 + k];
        f0[t] = a;
    }
    __syncthreads();
    float x0 = 0.f, bx = 0.f, bn = 0.f;
#pragma unroll
    for (int c = 0; c < 64; c++) {
        x0 += f0[c]     * w1x[t * 64 + c];
        bx += prep_b[c] * w1x[t * 64 + c];
        bn += prep_b[c] * w1n[t * 64 + c];
    }
    g_x0[t]          = x0;
    g_bias1[t]       = bx;
    g_bias1[128 + t] = bn;
}

// ---------------------------------------------------------------------------
// prep_W2: transpose/pack layer-2 weights: g_W2t[kp*512 + c*2 + e] = W_c[2kp+e]
// ---------------------------------------------------------------------------
__global__ void prep_W2(const float* __restrict__ w2x,
                        const float* __restrict__ w2n) {
    int idx = blockIdx.x * 256 + threadIdx.x;   // 0..131071
    int c = idx & 255, kk = idx >> 8;           // kk 0..511
    float v = (c < 128) ? w2x[c * 256 + kk] : w2n[(c - 128) * 256 + kk];
    g_W2t[(kk >> 1) * 512 + c * 2 + (kk & 1)] = v;
}

// ---------------------------------------------------------------------------
// mixed_kernel: block role by blockIdx.
//   bid <  nComp : compute role — 2 batches from chunk c-1 (round-3 body)
//   bid >= nComp : gather role  — warp = 1 sample of chunk c (round-3 body)
// Inter-chunk dependency satisfied by launch ordering; roles within a launch
// are independent, so gather overlaps compute across the chip.
// smem (compute role): A 16640 | F 3200 | H1 256 | mean 64 | bias 256
// ---------------------------------------------------------------------------
#define SMO_F   A_FLOATS
#define SMO_H1  (SMO_F + NS * 128)
#define SMO_MN  (SMO_H1 + 256)
#define SMO_B   (SMO_MN + 64)
#define SM_C_FLOATS (SMO_B + 256)              // 20416 floats = 81664 B

__global__ void __launch_bounds__(256)
mixed_kernel(const float* __restrict__ emb,
             const int* __restrict__ ids,
             const int* __restrict__ adj,
             const int* __restrict__ perm1,
             const int* __restrict__ perm2,
             int gBase, int cBase, int nComp) {
    extern __shared__ float sm[];
    const int t = threadIdx.x;
    const int bid = blockIdx.x;
    const float inv25 = 1.0f / 25.0f;

    if (bid >= nComp) {
        // ========================= GATHER ROLE =========================
        int w = t >> 5, lane = t & 31;
        int s = gBase * NS + (bid - nComp) * 8 + w;   // global sample index
        int i = s / NS;
        int j = s - i * NS;

        int id0 = __ldg(&ids[i]);
        int p1  = __ldg(&perm1[j]);
        int id1 = __ldg(&adj[(size_t)id0 * DEG + p1]);

        int p2  = __ldg(&perm2[lane < NS ? lane : 0]);
        int nb  = __ldg(&adj[(size_t)id1 * DEG + p2]);

        float2 e1 = *(const float2*)(emb + (size_t)id1 * 64 + 2 * lane);

        float sx = 0.f, sy = 0.f;
#pragma unroll
        for (int k = 0; k < NS; k++) {
            int idk = __shfl_sync(0xffffffffu, nb, k);
            float2 v = *(const float2*)(emb + (size_t)idk * 64 + 2 * lane);
            sx += v.x; sy += v.y;
        }
        float* dst = g_feats + (size_t)s * 128;
        *(float2*)(dst + 2 * lane)      = e1;
        *(float2*)(dst + 64 + 2 * lane) = make_float2(sx * inv25, sy * inv25);
        return;
    }

    // ========================= COMPUTE ROLE =========================
    float* sA    = sm;
    float* sF    = sm + SMO_F;
    float* sH1   = sm + SMO_H1;
    float* sMean = sm + SMO_MN;
    float* sBias = sm + SMO_B;

    // stage A (blocked layout, linear copy) + biases
    {
        const float4* src = (const float4*)g_At;
        float4* dst = (float4*)sA;
#pragma unroll
        for (int r = 0; r < 17; r++) {
            int idx = t + r * 256;
            if (idx < A_FLOATS / 4) dst[idx] = src[idx];
        }
        sBias[t] = g_bias1[t];
    }

    const int cg = t & 63;            // column group -> cols c0..c0+3
    const int sg = t >> 6;            // sample subset: s = sg + 4m
    const int c0 = cg * 4;
    const int kbase = (cg < 32) ? 0 : 64;   // e1-part vs mean2-part
    const float* Ab = sA + cg * A_GS;

    for (int b = 0; b < 2; b++) {
        const int i = cBase + bid * 2 + b;
        __syncthreads();              // A staged / prev iter done
        sH1[t] = 0.f;
        {
            const float4* fsrc = (const float4*)(g_feats + (size_t)i * NS * 128);
            float4* fdst = (float4*)sF;
#pragma unroll
            for (int r = 0; r < 4; r++) {
                int idx = t + r * 256;
                if (idx < NS * 32) fdst[idx] = fsrc[idx];
            }
        }
        __syncthreads();

        ull acc[7][4];
#pragma unroll
        for (int m = 0; m < 7; m++)
#pragma unroll
            for (int j = 0; j < 4; j++) acc[m][j] = 0ull;

#pragma unroll
        for (int k4 = 0; k4 < 16; k4++) {
            ulonglong2 a0 = *(const ulonglong2*)(Ab + k4 * 16);
            ulonglong2 a1 = *(const ulonglong2*)(Ab + k4 * 16 + 4);
            ulonglong2 a2 = *(const ulonglong2*)(Ab + k4 * 16 + 8);
            ulonglong2 a3 = *(const ulonglong2*)(Ab + k4 * 16 + 12);
#pragma unroll
            for (int m = 0; m < 7; m++) {
                int s = sg + 4 * m;
                if (s < NS) {
                    ulonglong2 f2 = *(const ulonglong2*)(sF + s * 128 + kbase + k4 * 4);
                    FFMA2(acc[m][0], f2.x, a0.x); FFMA2(acc[m][0], f2.y, a0.y);
                    FFMA2(acc[m][1], f2.x, a1.x); FFMA2(acc[m][1], f2.y, a1.y);
                    FFMA2(acc[m][2], f2.x, a2.x); FFMA2(acc[m][2], f2.y, a2.y);
                    FFMA2(acc[m][3], f2.x, a3.x); FFMA2(acc[m][3], f2.y, a3.y);
                }
            }
        }

        float hs[4] = {0.f, 0.f, 0.f, 0.f};
#pragma unroll
        for (int m = 0; m < 7; m++) {
            int s = sg + 4 * m;
            if (s < NS) {
#pragma unroll
                for (int j = 0; j < 4; j++) {
                    float lo = __uint_as_float((unsigned)acc[m][j]);
                    float hi = __uint_as_float((unsigned)(acc[m][j] >> 32));
                    hs[j] += fmaxf(lo + hi + sBias[c0 + j], 0.f);
                }
            }
        }
#pragma unroll
        for (int j = 0; j < 4; j++) atomicAdd(&sH1[c0 + j], hs[j]);

        // mean of e1 over 25 samples (for h0 neighbor branch)
        if (t < 64) {
            float m = 0.f;
#pragma unroll
            for (int s = 0; s < NS; s++) m += sF[s * 128 + t];
            sMean[t] = m * inv25;
        }
        __syncthreads();

        float* scr = g_scr + (size_t)i * 512;
        if (t < 128) {
            scr[t] = fmaxf(g_x0[t], 0.f);
        } else {
            int cgc = t >> 2, jc = t & 3;
            const float* Ac = sA + cgc * A_GS + jc * 4;
            float a = 0.f;
#pragma unroll
            for (int k4 = 0; k4 < 16; k4++) {
                float4 av = *(const float4*)(Ac + k4 * 16);
                float4 mv = *(const float4*)(sMean + k4 * 4);
                a += av.x * mv.x + av.y * mv.y + av.z * mv.z + av.w * mv.w;
            }
            scr[t] = fmaxf(a + sBias[t], 0.f);
        }
        scr[256 + t] = sH1[t] * inv25;
    }
}

// ---------------------------------------------------------------------------
// final2: layer-2 GEMM with packed transposed weights. 32 rows/block,
// thread = 4 cols x 8 rows; then L2-normalize + fc.  (proven in round 5)
// ---------------------------------------------------------------------------
__global__ void __launch_bounds__(256)
final2(const float* __restrict__ fcW,
       const float* __restrict__ fcb,
       float* __restrict__ out) {
    extern __shared__ float fsm[];
    float* in_sh = fsm;                 // 32 x 512
    float* sSq   = fsm + 32 * 512;      // 32
    float* sDot  = sSq + 32;            // 32

    int t  = threadIdx.x;
    int r0 = blockIdx.x * 32;

    {
        const float4* src = (const float4*)(g_scr + (size_t)r0 * 512);
        float4* dst = (float4*)in_sh;
#pragma unroll
        for (int q = 0; q < 16; q++) dst[t + q * 256] = src[t + q * 256];
    }
    if (t < 32) { sSq[t] = 0.f; sDot[t] = 0.f; }
    __syncthreads();

    const int c4 = (t & 63) * 4;            // 4 output cols
    const int rg = t >> 6;                  // row group (8 rows)
    const int ioff = (c4 < 128) ? 0 : 256;
    const float* xb = in_sh + rg * 8 * 512 + ioff;

    ull acc[8][4];
#pragma unroll
    for (int r = 0; r < 8; r++)
#pragma unroll
        for (int j = 0; j < 4; j++) acc[r][j] = 0ull;

#pragma unroll 4
    for (int kp = 0; kp < 128; kp++) {
        ulonglong2 wA = *(const ulonglong2*)(g_W2t + kp * 512 + c4 * 2);
        ulonglong2 wB = *(const ulonglong2*)(g_W2t + kp * 512 + c4 * 2 + 4);
#pragma unroll
        for (int r = 0; r < 8; r++) {
            ull x2 = *(const ull*)(xb + r * 512 + 2 * kp);
            FFMA2(acc[r][0], x2, wA.x);
            FFMA2(acc[r][1], x2, wA.y);
            FFMA2(acc[r][2], x2, wB.x);
            FFMA2(acc[r][3], x2, wB.y);
        }
    }

    float4 fw = *(const float4*)(fcW + c4);
    int lane = t & 31;
#pragma unroll
    for (int r = 0; r < 8; r++) {
        float v[4];
#pragma unroll
        for (int j = 0; j < 4; j++)
            v[j] = __uint_as_float((unsigned)acc[r][j])
                 + __uint_as_float((unsigned)(acc[r][j] >> 32));
        float sq = v[0]*v[0] + v[1]*v[1] + v[2]*v[2] + v[3]*v[3];
        float dt = v[0]*fw.x + v[1]*fw.y + v[2]*fw.z + v[3]*fw.w;
#pragma unroll
        for (int o = 16; o > 0; o >>= 1) {
            sq += __shfl_xor_sync(0xffffffffu, sq, o);
            dt += __shfl_xor_sync(0xffffffffu, dt, o);
        }
        if (lane == 0) {
            atomicAdd(&sSq[rg * 8 + r], sq);
            atomicAdd(&sDot[rg * 8 + r], dt);
        }
    }
    __syncthreads();
    if (t < 32) {
        float nrm = sqrtf(sSq[t]);
        out[r0 + t] = sDot[t] / fmaxf(nrm, 1e-12f) + fcb[0];
    }
}

// ---------------------------------------------------------------------------
extern "C" void kernel_launch(void* const* d_in, const int* in_sizes, int n_in,
                              void* d_out, int out_size) {
    const float* embedding = (const float*)d_in[0];
    const float* prep_W    = (const float*)d_in[1];
    const float* prep_b    = (const float*)d_in[2];
    const float* w1x       = (const float*)d_in[3];
    const float* w1n       = (const float*)d_in[4];
    const float* w2x       = (const float*)d_in[5];
    const float* w2n       = (const float*)d_in[6];
    const float* fcW       = (const float*)d_in[7];
    const float* fcb       = (const float*)d_in[8];
    const int*   ids       = (const int*)d_in[9];
    const int*   adj       = (const int*)d_in[10];
    const int*   perm1     = (const int*)d_in[11];
    const int*   perm2     = (const int*)d_in[12];
    const int n_nodes = in_sizes[0] / EMB - 1;

    prep_A<<<64, 128>>>(prep_W, w1x, w1n);
    prep_B<<<1, 128>>>(embedding, prep_W, prep_b, w1x, w1n, n_nodes);
    prep_W2<<<512, 256>>>(w2x, w2n);

    const int smem_c = SM_C_FLOATS * (int)sizeof(float);
    cudaFuncSetAttribute(mixed_kernel, cudaFuncAttributeMaxDynamicSharedMemorySize, smem_c);

    // Pipelined launches: L_c = compute(chunk c-1) ∥ gather(chunk c)
    for (int c = 0; c <= NCHUNK; c++) {
        int nComp   = (c >= 1)      ? CBLK : 0;
        int nGather = (c < NCHUNK)  ? GBLK : 0;
        int gBase   = c * CHUNK;             // batches gathered this launch
        int cBase   = (c - 1) * CHUNK;       // batches computed this launch
        mixed_kernel<<<nComp + nGather, 256, smem_c>>>(
            embedding, ids, adj, perm1, perm2, gBase, cBase, nComp);
    }

    const int smem_o = (32 * 512 + 64) * (int)sizeof(float);
    cudaFuncSetAttribute(final2, cudaFuncAttributeMaxDynamicSharedMemorySize, smem_o);
    final2<<<BATCH / 32, 256, smem_o>>>(fcW, fcb, (float*)d_out);
}

// round 10
// speedup vs baseline: 3.5435x; 1.0921x over previous
#include <cuda_runtime.h>
#include <cstdint>
#include <math.h>

#define EMB   64
#define NS    25
#define DEG   64
#define BATCH 4096
#define NSAMP (BATCH * NS)

typedef unsigned long long ull;

// fma.rn.f32x2 — packed fp32 FMA (Blackwell). acc += a*b (two lanes)
#define FFMA2(acc, a, b) \
    asm("fma.rn.f32x2 %0, %1, %2, %3;" : "=l"(acc) : "l"(a), "l"(b), "l"(acc))

// A layout: [64 colgroups][16 k4][4 cols][4 k], group stride 260 floats
#define A_GS 260
#define A_FLOATS (64 * A_GS)        // 16640 (full)
#define AH_FLOATS (32 * A_GS)       // 8320  (half: 128 cols)

// ---------------- static device scratch (no allocation) --------------------
__device__ float g_At[A_FLOATS];              // folded layer-1 weights, blocked
__device__ float g_bias1[256];                // [b1x ; b1n]
__device__ float g_x0[128];                   // feats0 @ w1x.T (pre-relu)
__device__ float g_W2t[512 * 256];            // layer-2 weights [128 kp][256 c][2]
__device__ float g_feats[(size_t)NSAMP * 128];// per sample: [e1(64)|mean2(64)]
__device__ float g_scr[(size_t)BATCH * 512];  // per batch: [h0cat(256)|h1mean(256)]

// ---------------------------------------------------------------------------
__global__ void prep_A(const float* __restrict__ prep_W,
                       const float* __restrict__ w1x,
                       const float* __restrict__ w1n) {
    int idx = blockIdx.x * 128 + threadIdx.x;   // 0..8191
    int k = idx >> 7, h = idx & 127;
    float ax = 0.f, an = 0.f;
#pragma unroll
    for (int c = 0; c < 64; c++) {
        float p = prep_W[c * 64 + k];
        ax += p * w1x[h * 64 + c];
        an += p * w1n[h * 64 + c];
    }
    int cx = h, cn = 128 + h;
    g_At[(cx >> 2) * A_GS + (k >> 2) * 16 + (cx & 3) * 4 + (k & 3)] = ax;
    g_At[(cn >> 2) * A_GS + (k >> 2) * 16 + (cn & 3) * 4 + (k & 3)] = an;
}

// ---------------------------------------------------------------------------
__global__ void prep_B(const float* __restrict__ emb,
                       const float* __restrict__ prep_W,
                       const float* __restrict__ prep_b,
                       const float* __restrict__ w1x,
                       const float* __restrict__ w1n,
                       int n_nodes) {
    __shared__ float f0[64];
    int t = threadIdx.x;
    if (t < 64) {
        const float* e = emb + (size_t)n_nodes * 64;
        float a = prep_b[t];
#pragma unroll
        for (int k = 0; k < 64; k++) a += e[k] * prep_W[t * 64 + k];
        f0[t] = a;
    }
    __syncthreads();
    float x0 = 0.f, bx = 0.f, bn = 0.f;
#pragma unroll
    for (int c = 0; c < 64; c++) {
        x0 += f0[c]     * w1x[t * 64 + c];
        bx += prep_b[c] * w1x[t * 64 + c];
        bn += prep_b[c] * w1n[t * 64 + c];
    }
    g_x0[t]          = x0;
    g_bias1[t]       = bx;
    g_bias1[128 + t] = bn;
}

// ---------------------------------------------------------------------------
__global__ void prep_W2(const float* __restrict__ w2x,
                        const float* __restrict__ w2n) {
    int idx = blockIdx.x * 256 + threadIdx.x;   // 0..131071
    int c = idx & 255, kk = idx >> 8;           // kk 0..511
    float v = (c < 128) ? w2x[c * 256 + kk] : w2n[(c - 128) * 256 + kk];
    g_W2t[(kk >> 1) * 512 + c * 2 + (kk & 1)] = v;
}

// ---------------------------------------------------------------------------
// gather_kernel: 1 warp = 1 sample (round-3 proven body).
// ---------------------------------------------------------------------------
__global__ void __launch_bounds__(256)
gather_kernel(const float* __restrict__ emb,
              const int* __restrict__ ids,
              const int* __restrict__ adj,
              const int* __restrict__ perm1,
              const int* __restrict__ perm2) {
    int t = threadIdx.x;
    int w = t >> 5, lane = t & 31;
    int s = blockIdx.x * 8 + w;                  // sample index
    int i = s / NS;
    int j = s - i * NS;

    int id0 = __ldg(&ids[i]);
    int p1  = __ldg(&perm1[j]);
    int id1 = __ldg(&adj[(size_t)id0 * DEG + p1]);

    int p2  = __ldg(&perm2[lane < NS ? lane : 0]);
    int nb  = __ldg(&adj[(size_t)id1 * DEG + p2]);

    float2 e1 = *(const float2*)(emb + (size_t)id1 * 64 + 2 * lane);

    float sx = 0.f, sy = 0.f;
#pragma unroll
    for (int k = 0; k < NS; k++) {
        int idk = __shfl_sync(0xffffffffu, nb, k);
        float2 v = *(const float2*)(emb + (size_t)idk * 64 + 2 * lane);
        sx += v.x; sy += v.y;
    }
    const float inv25 = 1.0f / 25.0f;
    float* dst = g_feats + (size_t)s * 128;
    *(float2*)(dst + 2 * lane)      = e1;
    *(float2*)(dst + 64 + 2 * lane) = make_float2(sx * inv25, sy * inv25);
}

// ---------------------------------------------------------------------------
// compute3: half-split compute. bid&1 selects x-half (cols 0-127) or n-half
// (cols 128-255); block handles 4 batches with cp.async double-buffered feats.
// smem floats: Ahalf 8320 | F 2x3200 | H1 128 | mean 64 | bias 128 = 15040
// -> 60.2 KB -> 3 blocks/SM.
// ---------------------------------------------------------------------------
#define SMO_F   AH_FLOATS                       // 8320
#define SMO_H1  (SMO_F + 2 * NS * 128)          // 14720
#define SMO_MN  (SMO_H1 + 128)                  // 14848
#define SMO_B   (SMO_MN + 64)                   // 14912
#define SM_C_FLOATS (SMO_B + 128)               // 15040

__device__ __forceinline__ void cp16(unsigned int saddr, const void* g) {
    asm volatile("cp.async.cg.shared.global [%0], [%1], 16;" :: "r"(saddr), "l"(g));
}

__global__ void __launch_bounds__(256)
compute3() {
    extern __shared__ float sm[];
    float* sA    = sm;
    float* sH1   = sm + SMO_H1;
    float* sMean = sm + SMO_MN;
    float* sBias = sm + SMO_B;

    const int t = threadIdx.x;
    const int half = blockIdx.x & 1;            // 0: x-cols, 1: n-cols
    const int grp  = blockIdx.x >> 1;           // batch group (4 batches)
    const float inv25 = 1.0f / 25.0f;

    // stage A half + bias
    {
        const float4* src = (const float4*)(g_At + half * AH_FLOATS);
        float4* dst = (float4*)sA;
#pragma unroll
        for (int r = 0; r < 9; r++) {
            int idx = t + r * 256;
            if (idx < AH_FLOATS / 4) dst[idx] = src[idx];
        }
        if (t < 128) { sBias[t] = g_bias1[half * 128 + t]; sH1[t] = 0.f; }
    }

    // prefetch feats for batch 0 of this group
    const int i0 = grp * 4;
    {
        unsigned int sbase = (unsigned int)__cvta_generic_to_shared(sm + SMO_F);
        const float4* g = (const float4*)(g_feats + (size_t)i0 * NS * 128);
#pragma unroll
        for (int r = 0; r < 4; r++) {
            int idx = t + r * 256;
            if (idx < NS * 32) cp16(sbase + idx * 16, g + idx);
        }
        asm volatile("cp.async.commit_group;" ::: "memory");
    }

    const int cg = t & 31;                 // column group -> local cols c0..c0+3
    const int sg = t >> 5;                 // sample subset: s = sg + 8m (m<4)
    const int c0 = cg * 4;
    const int kbase = half * 64;           // x-part reads e1, n-part reads mean2
    const float* Ab = sA + cg * A_GS;
    const float x0r = (t < 128) ? g_x0[t] : 0.f;

    for (int b = 0; b < 4; b++) {
        const int i = i0 + b;
        float* sFc = sm + SMO_F + (b & 1) * (NS * 128);

        if (b < 3) {   // prefetch next batch into other buffer
            unsigned int sbase = (unsigned int)__cvta_generic_to_shared(
                sm + SMO_F + ((b + 1) & 1) * (NS * 128));
            const float4* g = (const float4*)(g_feats + (size_t)(i + 1) * NS * 128);
#pragma unroll
            for (int r = 0; r < 4; r++) {
                int idx = t + r * 256;
                if (idx < NS * 32) cp16(sbase + idx * 16, g + idx);
            }
            asm volatile("cp.async.commit_group;" ::: "memory");
            asm volatile("cp.async.wait_group 1;" ::: "memory");
        } else {
            asm volatile("cp.async.wait_group 0;" ::: "memory");
        }
        __syncthreads();   // current feats visible; prev epilogue done

        const float* fb = sFc + kbase;
        ull acc[4][4];
#pragma unroll
        for (int m = 0; m < 4; m++)
#pragma unroll
            for (int j = 0; j < 4; j++) acc[m][j] = 0ull;

#pragma unroll
        for (int k4 = 0; k4 < 16; k4++) {
            ulonglong2 a0 = *(const ulonglong2*)(Ab + k4 * 16);
            ulonglong2 a1 = *(const ulonglong2*)(Ab + k4 * 16 + 4);
            ulonglong2 a2 = *(const ulonglong2*)(Ab + k4 * 16 + 8);
            ulonglong2 a3 = *(const ulonglong2*)(Ab + k4 * 16 + 12);
#pragma unroll
            for (int m = 0; m < 4; m++) {
                int s = sg + 8 * m;
                if (s < NS) {
                    ulonglong2 f2 = *(const ulonglong2*)(fb + s * 128 + k4 * 4);
                    FFMA2(acc[m][0], f2.x, a0.x); FFMA2(acc[m][0], f2.y, a0.y);
                    FFMA2(acc[m][1], f2.x, a1.x); FFMA2(acc[m][1], f2.y, a1.y);
                    FFMA2(acc[m][2], f2.x, a2.x); FFMA2(acc[m][2], f2.y, a2.y);
                    FFMA2(acc[m][3], f2.x, a3.x); FFMA2(acc[m][3], f2.y, a3.y);
                }
            }
        }

        float hs[4] = {0.f, 0.f, 0.f, 0.f};
#pragma unroll
        for (int m = 0; m < 4; m++) {
            int s = sg + 8 * m;
            if (s < NS) {
#pragma unroll
                for (int j = 0; j < 4; j++) {
                    float lo = __uint_as_float((unsigned)acc[m][j]);
                    float hi = __uint_as_float((unsigned)(acc[m][j] >> 32));
                    hs[j] += fmaxf(lo + hi + sBias[c0 + j], 0.f);
                }
            }
        }
#pragma unroll
        for (int j = 0; j < 4; j++) atomicAdd(&sH1[c0 + j], hs[j]);

        if (half == 1 && t < 64) {     // mean of e1 over samples (h0n input)
            float m = 0.f;
#pragma unroll
            for (int s = 0; s < NS; s++) m += sFc[s * 128 + t];
            sMean[t] = m * inv25;
        }
        __syncthreads();   // sH1 atomics + sMean done

        // ---- epilogue ----
        float* scr = g_scr + (size_t)i * 512;
        if (half == 0) {
            if (t < 128) {
                scr[t]       = fmaxf(x0r, 0.f);          // h0 x-part
                scr[256 + t] = sH1[t] * inv25;           // h1mean cols 0-127
                sH1[t] = 0.f;
            }
        } else {
            if (t < 128) {
                const float* Ac = sA + (t >> 2) * A_GS + (t & 3) * 4;
                float a = 0.f;
#pragma unroll
                for (int k4 = 0; k4 < 16; k4++) {
                    float4 av = *(const float4*)(Ac + k4 * 16);
                    float4 mv = *(const float4*)(sMean + k4 * 4);
                    a += av.x * mv.x + av.y * mv.y + av.z * mv.z + av.w * mv.w;
                }
                scr[128 + t] = fmaxf(a + sBias[t], 0.f); // h0 n-part
                scr[384 + t] = sH1[t] * inv25;           // h1mean cols 128-255
                sH1[t] = 0.f;
            }
        }
        __syncthreads();   // scr reads of sH1/sMean done before next batch
    }
}

// ---------------------------------------------------------------------------
// final2: layer-2 GEMM with packed transposed weights (proven). 32 rows/blk.
// ---------------------------------------------------------------------------
__global__ void __launch_bounds__(256)
final2(const float* __restrict__ fcW,
       const float* __restrict__ fcb,
       float* __restrict__ out) {
    extern __shared__ float fsm[];
    float* in_sh = fsm;                 // 32 x 512
    float* sSq   = fsm + 32 * 512;
    float* sDot  = sSq + 32;

    int t  = threadIdx.x;
    int r0 = blockIdx.x * 32;

    {
        const float4* src = (const float4*)(g_scr + (size_t)r0 * 512);
        float4* dst = (float4*)in_sh;
#pragma unroll
        for (int q = 0; q < 16; q++) dst[t + q * 256] = src[t + q * 256];
    }
    if (t < 32) { sSq[t] = 0.f; sDot[t] = 0.f; }
    __syncthreads();

    const int c4 = (t & 63) * 4;
    const int rg = t >> 6;
    const int ioff = (c4 < 128) ? 0 : 256;
    const float* xb = in_sh + rg * 8 * 512 + ioff;

    ull acc[8][4];
#pragma unroll
    for (int r = 0; r < 8; r++)
#pragma unroll
        for (int j = 0; j < 4; j++) acc[r][j] = 0ull;

#pragma unroll 4
    for (int kp = 0; kp < 128; kp++) {
        ulonglong2 wA = *(const ulonglong2*)(g_W2t + kp * 512 + c4 * 2);
        ulonglong2 wB = *(const ulonglong2*)(g_W2t + kp * 512 + c4 * 2 + 4);
#pragma unroll
        for (int r = 0; r < 8; r++) {
            ull x2 = *(const ull*)(xb + r * 512 + 2 * kp);
            FFMA2(acc[r][0], x2, wA.x);
            FFMA2(acc[r][1], x2, wA.y);
            FFMA2(acc[r][2], x2, wB.x);
            FFMA2(acc[r][3], x2, wB.y);
        }
    }

    float4 fw = *(const float4*)(fcW + c4);
    int lane = t & 31;
#pragma unroll
    for (int r = 0; r < 8; r++) {
        float v[4];
#pragma unroll
        for (int j = 0; j < 4; j++)
            v[j] = __uint_as_float((unsigned)acc[r][j])
                 + __uint_as_float((unsigned)(acc[r][j] >> 32));
        float sq = v[0]*v[0] + v[1]*v[1] + v[2]*v[2] + v[3]*v[3];
        float dt = v[0]*fw.x + v[1]*fw.y + v[2]*fw.z + v[3]*fw.w;
#pragma unroll
        for (int o = 16; o > 0; o >>= 1) {
            sq += __shfl_xor_sync(0xffffffffu, sq, o);
            dt += __shfl_xor_sync(0xffffffffu, dt, o);
        }
        if (lane == 0) {
            atomicAdd(&sSq[rg * 8 + r], sq);
            atomicAdd(&sDot[rg * 8 + r], dt);
        }
    }
    __syncthreads();
    if (t < 32) {
        float nrm = sqrtf(sSq[t]);
        out[r0 + t] = sDot[t] / fmaxf(nrm, 1e-12f) + fcb[0];
    }
}

// ---------------------------------------------------------------------------
extern "C" void kernel_launch(void* const* d_in, const int* in_sizes, int n_in,
                              void* d_out, int out_size) {
    const float* embedding = (const float*)d_in[0];
    const float* prep_W    = (const float*)d_in[1];
    const float* prep_b    = (const float*)d_in[2];
    const float* w1x       = (const float*)d_in[3];
    const float* w1n       = (const float*)d_in[4];
    const float* w2x       = (const float*)d_in[5];
    const float* w2n       = (const float*)d_in[6];
    const float* fcW       = (const float*)d_in[7];
    const float* fcb       = (const float*)d_in[8];
    const int*   ids       = (const int*)d_in[9];
    const int*   adj       = (const int*)d_in[10];
    const int*   perm1     = (const int*)d_in[11];
    const int*   perm2     = (const int*)d_in[12];
    const int n_nodes = in_sizes[0] / EMB - 1;

    prep_A<<<64, 128>>>(prep_W, w1x, w1n);
    prep_B<<<1, 128>>>(embedding, prep_W, prep_b, w1x, w1n, n_nodes);
    prep_W2<<<512, 256>>>(w2x, w2n);

    gather_kernel<<<NSAMP / 8, 256>>>(embedding, ids, adj, perm1, perm2);

    const int smem_c = SM_C_FLOATS * (int)sizeof(float);
    cudaFuncSetAttribute(compute3, cudaFuncAttributeMaxDynamicSharedMemorySize, smem_c);
    compute3<<<(BATCH / 4) * 2, 256, smem_c>>>();

    const int smem_o = (32 * 512 + 64) * (int)sizeof(float);
    cudaFuncSetAttribute(final2, cudaFuncAttributeMaxDynamicSharedMemorySize, smem_o);
    final2<<<BATCH / 32, 256, smem_o>>>(fcW, fcb, (float*)d_out);
}

// round 12
// speedup vs baseline: 3.9832x; 1.1241x over previous
#include <cuda_runtime.h>
#include <cstdint>
#include <math.h>

#define EMB   64
#define NS    25
#define DEG   64
#define BATCH 4096
#define NSAMP (BATCH * NS)

typedef unsigned long long ull;

// fma.rn.f32x2 — packed fp32 FMA (Blackwell). acc += a*b (two lanes)
#define FFMA2(acc, a, b) \
    asm("fma.rn.f32x2 %0, %1, %2, %3;" : "=l"(acc) : "l"(a), "l"(b), "l"(acc))

// A layout: [64 colgroups][16 k4][4 cols][4 k], group stride 260 floats
#define A_GS 260
#define A_FLOATS (64 * A_GS)    // 16640

// ---------------- static device scratch (no allocation) --------------------
__device__ float g_At[A_FLOATS];              // folded layer-1 weights, blocked
__device__ float g_bias1[256];                // [b1x ; b1n]
__device__ float g_x0[128];                   // feats0 @ w1x.T (pre-relu)
__device__ float g_W2t[512 * 256];            // layer-2 weights [128 kp][256 c][2]
__device__ float g_feats[(size_t)NSAMP * 128];// per sample: [e1(64)|mean2(64)]
__device__ float g_scr[(size_t)BATCH * 512];  // per batch: [h0cat(256)|h1mean(256)]

// ---------------------------------------------------------------------------
__global__ void prep_A(const float* __restrict__ prep_W,
                       const float* __restrict__ w1x,
                       const float* __restrict__ w1n) {
    int idx = blockIdx.x * 128 + threadIdx.x;   // 0..8191
    int k = idx >> 7, h = idx & 127;
    float ax = 0.f, an = 0.f;
#pragma unroll
    for (int c = 0; c < 64; c++) {
        float p = prep_W[c * 64 + k];
        ax += p * w1x[h * 64 + c];
        an += p * w1n[h * 64 + c];
    }
    int cx = h, cn = 128 + h;
    g_At[(cx >> 2) * A_GS + (k >> 2) * 16 + (cx & 3) * 4 + (k & 3)] = ax;
    g_At[(cn >> 2) * A_GS + (k >> 2) * 16 + (cn & 3) * 4 + (k & 3)] = an;
}

// ---------------------------------------------------------------------------
__global__ void prep_B(const float* __restrict__ emb,
                       const float* __restrict__ prep_W,
                       const float* __restrict__ prep_b,
                       const float* __restrict__ w1x,
                       const float* __restrict__ w1n,
                       int n_nodes) {
    __shared__ float f0[64];
    int t = threadIdx.x;
    if (t < 64) {
        const float* e = emb + (size_t)n_nodes * 64;
        float a = prep_b[t];
#pragma unroll
        for (int k = 0; k < 64; k++) a += e[k] * prep_W[t * 64 + k];
        f0[t] = a;
    }
    __syncthreads();
    float x0 = 0.f, bx = 0.f, bn = 0.f;
#pragma unroll
    for (int c = 0; c < 64; c++) {
        x0 += f0[c]     * w1x[t * 64 + c];
        bx += prep_b[c] * w1x[t * 64 + c];
        bn += prep_b[c] * w1n[t * 64 + c];
    }
    g_x0[t]          = x0;
    g_bias1[t]       = bx;
    g_bias1[128 + t] = bn;
}

// ---------------------------------------------------------------------------
__global__ void prep_W2(const float* __restrict__ w2x,
                        const float* __restrict__ w2n) {
    int idx = blockIdx.x * 256 + threadIdx.x;   // 0..131071
    int c = idx & 255, kk = idx >> 8;           // kk 0..511
    float v = (c < 128) ? w2x[c * 256 + kk] : w2n[(c - 128) * 256 + kk];
    g_W2t[(kk >> 1) * 512 + c * 2 + (kk & 1)] = v;
}

// ---------------------------------------------------------------------------
// gather_kernel: 1 warp = 1 sample (HBM-roofline proven: 88.7us, DRAM 79%).
// ---------------------------------------------------------------------------
__global__ void __launch_bounds__(256)
gather_kernel(const float* __restrict__ emb,
              const int* __restrict__ ids,
              const int* __restrict__ adj,
              const int* __restrict__ perm1,
              const int* __restrict__ perm2) {
    int t = threadIdx.x;
    int w = t >> 5, lane = t & 31;
    int s = blockIdx.x * 8 + w;                  // sample index
    int i = s / NS;
    int j = s - i * NS;

    int id0 = __ldg(&ids[i]);
    int p1  = __ldg(&perm1[j]);
    int id1 = __ldg(&adj[(size_t)id0 * DEG + p1]);

    int p2  = __ldg(&perm2[lane < NS ? lane : 0]);
    int nb  = __ldg(&adj[(size_t)id1 * DEG + p2]);

    float2 e1 = *(const float2*)(emb + (size_t)id1 * 64 + 2 * lane);

    float sx = 0.f, sy = 0.f;
#pragma unroll
    for (int k = 0; k < NS; k++) {
        int idk = __shfl_sync(0xffffffffu, nb, k);
        float2 v = *(const float2*)(emb + (size_t)idk * 64 + 2 * lane);
        sx += v.x; sy += v.y;
    }
    const float inv25 = 1.0f / 25.0f;
    float* dst = g_feats + (size_t)s * 128;
    *(float2*)(dst + 2 * lane)      = e1;
    *(float2*)(dst + 64 + 2 * lane) = make_float2(sx * inv25, sy * inv25);
}

// ---------------------------------------------------------------------------
// compute_kernel: PROVEN round-3 body (101us @ 2 batches), now 4 batches per
// block to amortize A staging. Thread owns 4 adjacent output columns x ~7
// samples. Conflict-free A loads, FFMA2-dense.
// smem: A 16640 + sF 3200 + sH1 256 + sMean 64 + sBias 256 = 20416 floats
// ---------------------------------------------------------------------------
#define SMO_F   A_FLOATS
#define SMO_H1  (SMO_F + NS * 128)
#define SMO_MN  (SMO_H1 + 256)
#define SMO_B   (SMO_MN + 64)
#define SM_C_FLOATS (SMO_B + 256)

__global__ void __launch_bounds__(256, 2)
compute_kernel() {
    extern __shared__ float sm[];
    float* sA    = sm;
    float* sF    = sm + SMO_F;
    float* sH1   = sm + SMO_H1;
    float* sMean = sm + SMO_MN;
    float* sBias = sm + SMO_B;

    int t = threadIdx.x;

    // stage A (blocked layout, linear copy) + biases
    {
        const float4* src = (const float4*)g_At;
        float4* dst = (float4*)sA;
#pragma unroll
        for (int r = 0; r < 17; r++) {
            int idx = t + r * 256;
            if (idx < A_FLOATS / 4) dst[idx] = src[idx];
        }
        sBias[t] = g_bias1[t];
    }

    const int cg = t & 63;            // column group -> cols c0..c0+3
    const int sg = t >> 6;            // sample subset: s = sg + 4m
    const int c0 = cg * 4;
    const int kbase = (cg < 32) ? 0 : 64;   // e1-part vs mean2-part
    const float* Ab = sA + cg * A_GS;
    const float inv25 = 1.0f / 25.0f;

    for (int b = 0; b < 4; b++) {
        const int i = blockIdx.x * 4 + b;
        __syncthreads();              // A staged / prev iter done
        sH1[t] = 0.f;
        {
            const float4* fsrc = (const float4*)(g_feats + (size_t)i * NS * 128);
            float4* fdst = (float4*)sF;
#pragma unroll
            for (int r = 0; r < 4; r++) {
                int idx = t + r * 256;
                if (idx < NS * 32) fdst[idx] = fsrc[idx];
            }
        }
        __syncthreads();

        ull acc[7][4];
#pragma unroll
        for (int m = 0; m < 7; m++)
#pragma unroll
            for (int j = 0; j < 4; j++) acc[m][j] = 0ull;

#pragma unroll
        for (int k4 = 0; k4 < 16; k4++) {
            ulonglong2 a0 = *(const ulonglong2*)(Ab + k4 * 16);
            ulonglong2 a1 = *(const ulonglong2*)(Ab + k4 * 16 + 4);
            ulonglong2 a2 = *(const ulonglong2*)(Ab + k4 * 16 + 8);
            ulonglong2 a3 = *(const ulonglong2*)(Ab + k4 * 16 + 12);
#pragma unroll
            for (int m = 0; m < 7; m++) {
                int s = sg + 4 * m;
                if (s < NS) {
                    ulonglong2 f2 = *(const ulonglong2*)(sF + s * 128 + kbase + k4 * 4);
                    FFMA2(acc[m][0], f2.x, a0.x); FFMA2(acc[m][0], f2.y, a0.y);
                    FFMA2(acc[m][1], f2.x, a1.x); FFMA2(acc[m][1], f2.y, a1.y);
                    FFMA2(acc[m][2], f2.x, a2.x); FFMA2(acc[m][2], f2.y, a2.y);
                    FFMA2(acc[m][3], f2.x, a3.x); FFMA2(acc[m][3], f2.y, a3.y);
                }
            }
        }

        float hs[4] = {0.f, 0.f, 0.f, 0.f};
#pragma unroll
        for (int m = 0; m < 7; m++) {
            int s = sg + 4 * m;
            if (s < NS) {
#pragma unroll
                for (int j = 0; j < 4; j++) {
                    float lo = __uint_as_float((unsigned)acc[m][j]);
                    float hi = __uint_as_float((unsigned)(acc[m][j] >> 32));
                    hs[j] += fmaxf(lo + hi + sBias[c0 + j], 0.f);
                }
            }
        }
#pragma unroll
        for (int j = 0; j < 4; j++) atomicAdd(&sH1[c0 + j], hs[j]);

        // mean of e1 over 25 samples (for h0 neighbor branch)
        if (t < 64) {
            float m = 0.f;
#pragma unroll
            for (int s = 0; s < NS; s++) m += sF[s * 128 + t];
            sMean[t] = m * inv25;
        }
        __syncthreads();

        float* scr = g_scr + (size_t)i * 512;
        if (t < 128) {
            scr[t] = fmaxf(g_x0[t], 0.f);
        } else {
            int cgc = t >> 2, jc = t & 3;
            const float* Ac = sA + cgc * A_GS + jc * 4;
            float a = 0.f;
#pragma unroll
            for (int k4 = 0; k4 < 16; k4++) {
                float4 av = *(const float4*)(Ac + k4 * 16);
                float4 mv = *(const float4*)(sMean + k4 * 4);
                a += av.x * mv.x + av.y * mv.y + av.z * mv.z + av.w * mv.w;
            }
            scr[t] = fmaxf(a + sBias[t], 0.f);
        }
        scr[256 + t] = sH1[t] * inv25;
    }
}

// ---------------------------------------------------------------------------
// final2: layer-2 GEMM with packed transposed weights (proven). 32 rows/blk.
// ---------------------------------------------------------------------------
__global__ void __launch_bounds__(256)
final2(const float* __restrict__ fcW,
       const float* __restrict__ fcb,
       float* __restrict__ out) {
    extern __shared__ float fsm[];
    float* in_sh = fsm;                 // 32 x 512
    float* sSq   = fsm + 32 * 512;
    float* sDot  = sSq + 32;

    int t  = threadIdx.x;
    int r0 = blockIdx.x * 32;

    {
        const float4* src = (const float4*)(g_scr + (size_t)r0 * 512);
        float4* dst = (float4*)in_sh;
#pragma unroll
        for (int q = 0; q < 16; q++) dst[t + q * 256] = src[t + q * 256];
    }
    if (t < 32) { sSq[t] = 0.f; sDot[t] = 0.f; }
    __syncthreads();

    const int c4 = (t & 63) * 4;
    const int rg = t >> 6;
    const int ioff = (c4 < 128) ? 0 : 256;
    const float* xb = in_sh + rg * 8 * 512 + ioff;

    ull acc[8][4];
#pragma unroll
    for (int r = 0; r < 8; r++)
#pragma unroll
        for (int j = 0; j < 4; j++) acc[r][j] = 0ull;

#pragma unroll 4
    for (int kp = 0; kp < 128; kp++) {
        ulonglong2 wA = *(const ulonglong2*)(g_W2t + kp * 512 + c4 * 2);
        ulonglong2 wB = *(const ulonglong2*)(g_W2t + kp * 512 + c4 * 2 + 4);
#pragma unroll
        for (int r = 0; r < 8; r++) {
            ull x2 = *(const ull*)(xb + r * 512 + 2 * kp);
            FFMA2(acc[r][0], x2, wA.x);
            FFMA2(acc[r][1], x2, wA.y);
            FFMA2(acc[r][2], x2, wB.x);
            FFMA2(acc[r][3], x2, wB.y);
        }
    }

    float4 fw = *(const float4*)(fcW + c4);
    int lane = t & 31;
#pragma unroll
    for (int r = 0; r < 8; r++) {
        float v[4];
#pragma unroll
        for (int j = 0; j < 4; j++)
            v[j] = __uint_as_float((unsigned)acc[r][j])
                 + __uint_as_float((unsigned)(acc[r][j] >> 32));
        float sq = v[0]*v[0] + v[1]*v[1] + v[2]*v[2] + v[3]*v[3];
        float dt = v[0]*fw.x + v[1]*fw.y + v[2]*fw.z + v[3]*fw.w;
#pragma unroll
        for (int o = 16; o > 0; o >>= 1) {
            sq += __shfl_xor_sync(0xffffffffu, sq, o);
            dt += __shfl_xor_sync(0xffffffffu, dt, o);
        }
        if (lane == 0) {
            atomicAdd(&sSq[rg * 8 + r], sq);
            atomicAdd(&sDot[rg * 8 + r], dt);
        }
    }
    __syncthreads();
    if (t < 32) {
        float nrm = sqrtf(sSq[t]);
        out[r0 + t] = sDot[t] / fmaxf(nrm, 1e-12f) + fcb[0];
    }
}

// ---------------------------------------------------------------------------
extern "C" void kernel_launch(void* const* d_in, const int* in_sizes, int n_in,
                              void* d_out, int out_size) {
    const float* embedding = (const float*)d_in[0];
    const float* prep_W    = (const float*)d_in[1];
    const float* prep_b    = (const float*)d_in[2];
    const float* w1x       = (const float*)d_in[3];
    const float* w1n       = (const float*)d_in[4];
    const float* w2x       = (const float*)d_in[5];
    const float* w2n       = (const float*)d_in[6];
    const float* fcW       = (const float*)d_in[7];
    const float* fcb       = (const float*)d_in[8];
    const int*   ids       = (const int*)d_in[9];
    const int*   adj       = (const int*)d_in[10];
    const int*   perm1     = (const int*)d_in[11];
    const int*   perm2     = (const int*)d_in[12];
    const int n_nodes = in_sizes[0] / EMB - 1;

    prep_A<<<64, 128>>>(prep_W, w1x, w1n);
    prep_B<<<1, 128>>>(embedding, prep_W, prep_b, w1x, w1n, n_nodes);
    prep_W2<<<512, 256>>>(w2x, w2n);

    gather_kernel<<<NSAMP / 8, 256>>>(embedding, ids, adj, perm1, perm2);

    const int smem_c = SM_C_FLOATS * (int)sizeof(float);
    cudaFuncSetAttribute(compute_kernel, cudaFuncAttributeMaxDynamicSharedMemorySize, smem_c);
    compute_kernel<<<BATCH / 4, 256, smem_c>>>();

    const int smem_o = (32 * 512 + 64) * (int)sizeof(float);
    cudaFuncSetAttribute(final2, cudaFuncAttributeMaxDynamicSharedMemorySize, smem_o);
    final2<<<BATCH / 32, 256, smem_o>>>(fcW, fcb, (float*)d_out);
}

// round 14
// speedup vs baseline: 4.4413x; 1.1150x over previous
#include <cuda_runtime.h>
#include <cstdint>
#include <math.h>

#define EMB   64
#define NS    25
#define DEG   64
#define BATCH 4096
#define NSAMP (BATCH * NS)
#define FR    68                      // shared feat row stride (conflict-free)

typedef unsigned long long ull;

// fma.rn.f32x2 — packed fp32 FMA (Blackwell). acc += a*b (two lanes)
#define FFMA2(acc, a, b) \
    asm("fma.rn.f32x2 %0, %1, %2, %3;" : "=l"(acc) : "l"(a), "l"(b), "l"(acc))

#define CVT_TF32(u, f) \
    asm("cvt.rna.tf32.f32 %0, %1;" : "=r"(u) : "f"(f))

#define MMA_TF32(c0, c1, c2, c3, a0, a1, a2, a3, b0, b1)                     \
    asm("mma.sync.aligned.m16n8k8.row.col.f32.tf32.tf32.f32 "                \
        "{%0,%1,%2,%3},{%4,%5,%6,%7},{%8,%9},{%0,%1,%2,%3};"                 \
        : "+f"(c0), "+f"(c1), "+f"(c2), "+f"(c3)                             \
        : "r"(a0), "r"(a1), "r"(a2), "r"(a3), "r"(b0), "r"(b1))

// ---------------- static device scratch (no allocation) --------------------
__device__ float g_Atc[256 * 64];             // folded layer-1 weights [c][k]
__device__ float g_bias1[256];                // [b1x ; b1n]
__device__ float g_x0[128];                   // feats0 @ w1x.T (pre-relu)
__device__ float g_W2t[512 * 256];            // layer-2 weights [128 kp][256 c][2]
__device__ float g_feats[(size_t)NSAMP * 128];// per sample: [e1(64)|mean2(64)]
__device__ float g_scr[(size_t)BATCH * 512];  // per batch: [h0cat(256)|h1mean(256)]

// ---------------------------------------------------------------------------
__global__ void prep_A(const float* __restrict__ prep_W,
                       const float* __restrict__ w1x,
                       const float* __restrict__ w1n) {
    int idx = blockIdx.x * 128 + threadIdx.x;   // 0..8191
    int k = idx >> 7, h = idx & 127;
    float ax = 0.f, an = 0.f;
#pragma unroll
    for (int c = 0; c < 64; c++) {
        float p = prep_W[c * 64 + k];
        ax += p * w1x[h * 64 + c];
        an += p * w1n[h * 64 + c];
    }
    g_Atc[h * 64 + k]         = ax;
    g_Atc[(128 + h) * 64 + k] = an;
}

// ---------------------------------------------------------------------------
__global__ void prep_B(const float* __restrict__ emb,
                       const float* __restrict__ prep_W,
                       const float* __restrict__ prep_b,
                       const float* __restrict__ w1x,
                       const float* __restrict__ w1n,
                       int n_nodes) {
    __shared__ float f0[64];
    int t = threadIdx.x;
    if (t < 64) {
        const float* e = emb + (size_t)n_nodes * 64;
        float a = prep_b[t];
#pragma unroll
        for (int k = 0; k < 64; k++) a += e[k] * prep_W[t * 64 + k];
        f0[t] = a;
    }
    __syncthreads();
    float x0 = 0.f, bx = 0.f, bn = 0.f;
#pragma unroll
    for (int c = 0; c < 64; c++) {
        x0 += f0[c]     * w1x[t * 64 + c];
        bx += prep_b[c] * w1x[t * 64 + c];
        bn += prep_b[c] * w1n[t * 64 + c];
    }
    g_x0[t]          = x0;
    g_bias1[t]       = bx;
    g_bias1[128 + t] = bn;
}

// ---------------------------------------------------------------------------
__global__ void prep_W2(const float* __restrict__ w2x,
                        const float* __restrict__ w2n) {
    int idx = blockIdx.x * 256 + threadIdx.x;   // 0..131071
    int c = idx & 255, kk = idx >> 8;           // kk 0..511
    float v = (c < 128) ? w2x[c * 256 + kk] : w2n[(c - 128) * 256 + kk];
    g_W2t[(kk >> 1) * 512 + c * 2 + (kk & 1)] = v;
}

// ---------------------------------------------------------------------------
// gather_kernel: 1 warp = 1 sample (HBM-roofline proven: 87us, DRAM 80%).
// ---------------------------------------------------------------------------
__global__ void __launch_bounds__(256)
gather_kernel(const float* __restrict__ emb,
              const int* __restrict__ ids,
              const int* __restrict__ adj,
              const int* __restrict__ perm1,
              const int* __restrict__ perm2) {
    int t = threadIdx.x;
    int w = t >> 5, lane = t & 31;
    int s = blockIdx.x * 8 + w;                  // sample index
    int i = s / NS;
    int j = s - i * NS;

    int id0 = __ldg(&ids[i]);
    int p1  = __ldg(&perm1[j]);
    int id1 = __ldg(&adj[(size_t)id0 * DEG + p1]);

    int p2  = __ldg(&perm2[lane < NS ? lane : 0]);
    int nb  = __ldg(&adj[(size_t)id1 * DEG + p2]);

    float2 e1 = *(const float2*)(emb + (size_t)id1 * 64 + 2 * lane);

    float sx = 0.f, sy = 0.f;
#pragma unroll
    for (int k = 0; k < NS; k++) {
        int idk = __shfl_sync(0xffffffffu, nb, k);
        float2 v = *(const float2*)(emb + (size_t)idk * 64 + 2 * lane);
        sx += v.x; sy += v.y;
    }
    const float inv25 = 1.0f / 25.0f;
    float* dst = g_feats + (size_t)s * 128;
    *(float2*)(dst + 2 * lane)      = e1;
    *(float2*)(dst + 64 + 2 * lane) = make_float2(sx * inv25, sy * inv25);
}

// ---------------------------------------------------------------------------
// compute_mma: layer-1 via tf32 mma.sync. 8 warps/block, warp owns 32 output
// cols; folded weights as B-fragments in registers (loaded once per block).
// Per batch: stage feats (rows 0-24; row 25 of n-half = mean1), mma, epilogue.
// Row mapping (m16n8k8): A a0=(g,t4) a1=(g+8,t4) a2=(g,t4+4) a3=(g+8,t4+4);
// B b0=(t4,g) b1=(t4+4,g); C c0=(g,2t4) c1=(g,2t4+1) c2=(g+8,2t4) c3=(g+8,2t4+1).
// ---------------------------------------------------------------------------
#define BPB 8   // batches per block

__global__ void __launch_bounds__(256)
compute_mma() {
    __shared__ float Fx[32 * FR];
    __shared__ float Fn[32 * FR];

    const int t = threadIdx.x;
    const int w = t >> 5, lane = t & 31;
    const int g = lane >> 2, t4 = lane & 3;
    const int wcol = w * 32;                  // global output col base
    const bool isN = (w >= 4);
    const float* Fw = isN ? Fn : Fx;
    const float inv25 = 1.0f / 25.0f;

    // ---- load B fragments (weights) once: b[n8][k8][2] ----
    unsigned bfr[4][8][2];
#pragma unroll
    for (int n8 = 0; n8 < 4; n8++) {
        int c = wcol + n8 * 8 + g;
#pragma unroll
        for (int k8 = 0; k8 < 8; k8++) {
            float v0 = g_Atc[c * 64 + k8 * 8 + t4];
            float v1 = g_Atc[c * 64 + k8 * 8 + t4 + 4];
            CVT_TF32(bfr[n8][k8][0], v0);
            CVT_TF32(bfr[n8][k8][1], v1);
        }
    }
    float biasE[4], biasO[4];
#pragma unroll
    for (int n8 = 0; n8 < 4; n8++) {
        biasE[n8] = g_bias1[wcol + n8 * 8 + 2 * t4];
        biasO[n8] = g_bias1[wcol + n8 * 8 + 2 * t4 + 1];
    }
    const float x0v = (t < 128) ? g_x0[t] : 0.f;

    for (int b8 = 0; b8 < BPB; b8++) {
        const int i = blockIdx.x * BPB + b8;
        __syncthreads();              // previous epilogue reads done
        // ---- stage feats: 25 rows x 16 float4 each half ----
        {
            const float4* src = (const float4*)(g_feats + (size_t)i * NS * 128);
#pragma unroll
            for (int idx = t; idx < 400; idx += 256) {
                int s = idx >> 4, q = idx & 15;
                float4 ve = src[s * 32 + q];
                float4 vn = src[s * 32 + 16 + q];
                *(float4*)(Fx + s * FR + q * 4) = ve;
                *(float4*)(Fn + s * FR + q * 4) = vn;
            }
        }
        __syncthreads();
        if (t < 64) {                 // mean1 -> Fn row 25
            float m = 0.f;
#pragma unroll
            for (int s = 0; s < NS; s++) m += Fx[s * FR + t];
            Fn[25 * FR + t] = m * inv25;
        }
        __syncthreads();

        // ---- mma ----
        float cfr[2][4][4];
#pragma unroll
        for (int m = 0; m < 2; m++)
#pragma unroll
            for (int n8 = 0; n8 < 4; n8++)
#pragma unroll
                for (int q = 0; q < 4; q++) cfr[m][n8][q] = 0.f;

#pragma unroll
        for (int m = 0; m < 2; m++) {
            int rb = m * 16;
#pragma unroll
            for (int k8 = 0; k8 < 8; k8++) {
                unsigned a0, a1, a2, a3;
                CVT_TF32(a0, Fw[(rb + g) * FR + k8 * 8 + t4]);
                CVT_TF32(a1, Fw[(rb + g + 8) * FR + k8 * 8 + t4]);
                CVT_TF32(a2, Fw[(rb + g) * FR + k8 * 8 + t4 + 4]);
                CVT_TF32(a3, Fw[(rb + g + 8) * FR + k8 * 8 + t4 + 4]);
#pragma unroll
                for (int n8 = 0; n8 < 4; n8++)
                    MMA_TF32(cfr[m][n8][0], cfr[m][n8][1], cfr[m][n8][2], cfr[m][n8][3],
                             a0, a1, a2, a3, bfr[n8][k8][0], bfr[n8][k8][1]);
            }
        }

        // ---- epilogue ----
        float* scr = g_scr + (size_t)i * 512;
        if (t < 128) scr[t] = fmaxf(x0v, 0.f);     // h0 x-part
#pragma unroll
        for (int n8 = 0; n8 < 4; n8++) {
            // rows: tile0 c0/c1 -> s=g, c2/c3 -> s=8+g; tile1 c0/c1 -> s=16+g
            // tile1 c2/c3 -> s=24+g (valid for sum only g==0; g==1 is mean1 row)
            float vE = fmaxf(cfr[0][n8][0] + biasE[n8], 0.f)
                     + fmaxf(cfr[0][n8][2] + biasE[n8], 0.f)
                     + fmaxf(cfr[1][n8][0] + biasE[n8], 0.f);
            float vO = fmaxf(cfr[0][n8][1] + biasO[n8], 0.f)
                     + fmaxf(cfr[0][n8][3] + biasO[n8], 0.f)
                     + fmaxf(cfr[1][n8][1] + biasO[n8], 0.f);
            if (g == 0) {
                vE += fmaxf(cfr[1][n8][2] + biasE[n8], 0.f);
                vO += fmaxf(cfr[1][n8][3] + biasO[n8], 0.f);
            }
            if (isN && g == 1) {       // row 25 = mean1 @ A1n -> h0 n-part
                scr[wcol + n8 * 8 + 2 * t4]     = fmaxf(cfr[1][n8][2] + biasE[n8], 0.f);
                scr[wcol + n8 * 8 + 2 * t4 + 1] = fmaxf(cfr[1][n8][3] + biasO[n8], 0.f);
            }
#pragma unroll
            for (int o = 4; o < 32; o <<= 1) {
                vE += __shfl_xor_sync(0xffffffffu, vE, o);
                vO += __shfl_xor_sync(0xffffffffu, vO, o);
            }
            if (lane < 4) {
                scr[256 + wcol + n8 * 8 + 2 * lane]     = vE * inv25;
                scr[256 + wcol + n8 * 8 + 2 * lane + 1] = vO * inv25;
            }
        }
    }
}

// ---------------------------------------------------------------------------
// final2: layer-2 GEMM with packed transposed weights (proven). 32 rows/blk.
// ---------------------------------------------------------------------------
__global__ void __launch_bounds__(256)
final2(const float* __restrict__ fcW,
       const float* __restrict__ fcb,
       float* __restrict__ out) {
    extern __shared__ float fsm[];
    float* in_sh = fsm;                 // 32 x 512
    float* sSq   = fsm + 32 * 512;
    float* sDot  = sSq + 32;

    int t  = threadIdx.x;
    int r0 = blockIdx.x * 32;

    {
        const float4* src = (const float4*)(g_scr + (size_t)r0 * 512);
        float4* dst = (float4*)in_sh;
#pragma unroll
        for (int q = 0; q < 16; q++) dst[t + q * 256] = src[t + q * 256];
    }
    if (t < 32) { sSq[t] = 0.f; sDot[t] = 0.f; }
    __syncthreads();

    const int c4 = (t & 63) * 4;
    const int rg = t >> 6;
    const int ioff = (c4 < 128) ? 0 : 256;
    const float* xb = in_sh + rg * 8 * 512 + ioff;

    ull acc[8][4];
#pragma unroll
    for (int r = 0; r < 8; r++)
#pragma unroll
        for (int j = 0; j < 4; j++) acc[r][j] = 0ull;

#pragma unroll 4
    for (int kp = 0; kp < 128; kp++) {
        ulonglong2 wA = *(const ulonglong2*)(g_W2t + kp * 512 + c4 * 2);
        ulonglong2 wB = *(const ulonglong2*)(g_W2t + kp * 512 + c4 * 2 + 4);
#pragma unroll
        for (int r = 0; r < 8; r++) {
            ull x2 = *(const ull*)(xb + r * 512 + 2 * kp);
            FFMA2(acc[r][0], x2, wA.x);
            FFMA2(acc[r][1], x2, wA.y);
            FFMA2(acc[r][2], x2, wB.x);
            FFMA2(acc[r][3], x2, wB.y);
        }
    }

    float4 fw = *(const float4*)(fcW + c4);
    int lane = t & 31;
#pragma unroll
    for (int r = 0; r < 8; r++) {
        float v[4];
#pragma unroll
        for (int j = 0; j < 4; j++)
            v[j] = __uint_as_float((unsigned)acc[r][j])
                 + __uint_as_float((unsigned)(acc[r][j] >> 32));
        float sq = v[0]*v[0] + v[1]*v[1] + v[2]*v[2] + v[3]*v[3];
        float dt = v[0]*fw.x + v[1]*fw.y + v[2]*fw.z + v[3]*fw.w;
#pragma unroll
        for (int o = 16; o > 0; o >>= 1) {
            sq += __shfl_xor_sync(0xffffffffu, sq, o);
            dt += __shfl_xor_sync(0xffffffffu, dt, o);
        }
        if (lane == 0) {
            atomicAdd(&sSq[rg * 8 + r], sq);
            atomicAdd(&sDot[rg * 8 + r], dt);
        }
    }
    __syncthreads();
    if (t < 32) {
        float nrm = sqrtf(sSq[t]);
        out[r0 + t] = sDot[t] / fmaxf(nrm, 1e-12f) + fcb[0];
    }
}

// ---------------------------------------------------------------------------
extern "C" void kernel_launch(void* const* d_in, const int* in_sizes, int n_in,
                              void* d_out, int out_size) {
    const float* embedding = (const float*)d_in[0];
    const float* prep_W    = (const float*)d_in[1];
    const float* prep_b    = (const float*)d_in[2];
    const float* w1x       = (const float*)d_in[3];
    const float* w1n       = (const float*)d_in[4];
    const float* w2x       = (const float*)d_in[5];
    const float* w2n       = (const float*)d_in[6];
    const float* fcW       = (const float*)d_in[7];
    const float* fcb       = (const float*)d_in[8];
    const int*   ids       = (const int*)d_in[9];
    const int*   adj       = (const int*)d_in[10];
    const int*   perm1     = (const int*)d_in[11];
    const int*   perm2     = (const int*)d_in[12];
    const int n_nodes = in_sizes[0] / EMB - 1;

    prep_A<<<64, 128>>>(prep_W, w1x, w1n);
    prep_B<<<1, 128>>>(embedding, prep_W, prep_b, w1x, w1n, n_nodes);
    prep_W2<<<512, 256>>>(w2x, w2n);

    gather_kernel<<<NSAMP / 8, 256>>>(embedding, ids, adj, perm1, perm2);

    compute_mma<<<BATCH / BPB, 256>>>();

    const int smem_o = (32 * 512 + 64) * (int)sizeof(float);
    cudaFuncSetAttribute(final2, cudaFuncAttributeMaxDynamicSharedMemorySize, smem_o);
    final2<<<BATCH / 32, 256, smem_o>>>(fcW, fcb, (float*)d_out);
}

// round 15
// speedup vs baseline: 5.2048x; 1.1719x over previous
#include <cuda_runtime.h>
#include <cstdint>
#include <math.h>

#define EMB   64
#define NS    25
#define DEG   64
#define BATCH 4096
#define NSAMP (BATCH * NS)
#define FR    68                      // shared feat row stride (conflict-free)
#define CGRID 296                     // persistent compute blocks (2/SM)

typedef unsigned long long ull;

// fma.rn.f32x2 — packed fp32 FMA (Blackwell). acc += a*b (two lanes)
#define FFMA2(acc, a, b) \
    asm("fma.rn.f32x2 %0, %1, %2, %3;" : "=l"(acc) : "l"(a), "l"(b), "l"(acc))

#define CVT_TF32(u, f) \
    asm("cvt.rna.tf32.f32 %0, %1;" : "=r"(u) : "f"(f))

#define MMA_TF32(c0, c1, c2, c3, a0, a1, a2, a3, b0, b1)                     \
    asm("mma.sync.aligned.m16n8k8.row.col.f32.tf32.tf32.f32 "                \
        "{%0,%1,%2,%3},{%4,%5,%6,%7},{%8,%9},{%0,%1,%2,%3};"                 \
        : "+f"(c0), "+f"(c1), "+f"(c2), "+f"(c3)                             \
        : "r"(a0), "r"(a1), "r"(a2), "r"(a3), "r"(b0), "r"(b1))

// ---------------- static device scratch (no allocation) --------------------
__device__ float g_Atc[256 * 64];             // folded layer-1 weights [c][k]
__device__ float g_bias1[256];                // [b1x ; b1n]
__device__ float g_x0[128];                   // feats0 @ w1x.T (pre-relu)
__device__ float g_W2t[512 * 256];            // layer-2 weights [128 kp][256 c][2]
__device__ float g_feats[(size_t)NSAMP * 128];// per sample: [e1(64)|mean2(64)]
__device__ float g_scr[(size_t)BATCH * 512];  // per batch: [h0cat(256)|h1mean(256)]

// ---------------------------------------------------------------------------
__global__ void prep_A(const float* __restrict__ prep_W,
                       const float* __restrict__ w1x,
                       const float* __restrict__ w1n) {
    int idx = blockIdx.x * 128 + threadIdx.x;   // 0..8191
    int k = idx >> 7, h = idx & 127;
    float ax = 0.f, an = 0.f;
#pragma unroll
    for (int c = 0; c < 64; c++) {
        float p = prep_W[c * 64 + k];
        ax += p * w1x[h * 64 + c];
        an += p * w1n[h * 64 + c];
    }
    g_Atc[h * 64 + k]         = ax;
    g_Atc[(128 + h) * 64 + k] = an;
}

// ---------------------------------------------------------------------------
__global__ void prep_B(const float* __restrict__ emb,
                       const float* __restrict__ prep_W,
                       const float* __restrict__ prep_b,
                       const float* __restrict__ w1x,
                       const float* __restrict__ w1n,
                       int n_nodes) {
    __shared__ float f0[64];
    int t = threadIdx.x;
    if (t < 64) {
        const float* e = emb + (size_t)n_nodes * 64;
        float a = prep_b[t];
#pragma unroll
        for (int k = 0; k < 64; k++) a += e[k] * prep_W[t * 64 + k];
        f0[t] = a;
    }
    __syncthreads();
    float x0 = 0.f, bx = 0.f, bn = 0.f;
#pragma unroll
    for (int c = 0; c < 64; c++) {
        x0 += f0[c]     * w1x[t * 64 + c];
        bx += prep_b[c] * w1x[t * 64 + c];
        bn += prep_b[c] * w1n[t * 64 + c];
    }
    g_x0[t]          = x0;
    g_bias1[t]       = bx;
    g_bias1[128 + t] = bn;
}

// ---------------------------------------------------------------------------
__global__ void prep_W2(const float* __restrict__ w2x,
                        const float* __restrict__ w2n) {
    int idx = blockIdx.x * 256 + threadIdx.x;   // 0..131071
    int c = idx & 255, kk = idx >> 8;           // kk 0..511
    float v = (c < 128) ? w2x[c * 256 + kk] : w2n[(c - 128) * 256 + kk];
    g_W2t[(kk >> 1) * 512 + c * 2 + (kk & 1)] = v;
}

// ---------------------------------------------------------------------------
// gather_kernel: 1 warp = 1 sample (HBM-roofline proven: ~88us, DRAM 80%).
// ---------------------------------------------------------------------------
__global__ void __launch_bounds__(256)
gather_kernel(const float* __restrict__ emb,
              const int* __restrict__ ids,
              const int* __restrict__ adj,
              const int* __restrict__ perm1,
              const int* __restrict__ perm2) {
    int t = threadIdx.x;
    int w = t >> 5, lane = t & 31;
    int s = blockIdx.x * 8 + w;                  // sample index
    int i = s / NS;
    int j = s - i * NS;

    int id0 = __ldg(&ids[i]);
    int p1  = __ldg(&perm1[j]);
    int id1 = __ldg(&adj[(size_t)id0 * DEG + p1]);

    int p2  = __ldg(&perm2[lane < NS ? lane : 0]);
    int nb  = __ldg(&adj[(size_t)id1 * DEG + p2]);

    float2 e1 = *(const float2*)(emb + (size_t)id1 * 64 + 2 * lane);

    float sx = 0.f, sy = 0.f;
#pragma unroll
    for (int k = 0; k < NS; k++) {
        int idk = __shfl_sync(0xffffffffu, nb, k);
        float2 v = *(const float2*)(emb + (size_t)idk * 64 + 2 * lane);
        sx += v.x; sy += v.y;
    }
    const float inv25 = 1.0f / 25.0f;
    float* dst = g_feats + (size_t)s * 128;
    *(float2*)(dst + 2 * lane)      = e1;
    *(float2*)(dst + 64 + 2 * lane) = make_float2(sx * inv25, sy * inv25);
}

// ---------------------------------------------------------------------------
// compute_mma: persistent tf32 mma.sync compute. 296 blocks (2/SM), grid-
// stride over batches, cp.async double-buffered feat staging.
// Warp owns 32 output cols; folded weights live in registers (loaded once).
// Row mapping (m16n8k8): A a0=(g,t4) a1=(g+8,t4) a2=(g,t4+4) a3=(g+8,t4+4);
// B b0=(t4,g) b1=(t4+4,g); C c0=(g,2t4) c1=(g,2t4+1) c2=(g+8,2t4) c3=(g+8,2t4+1).
// smem: 2 buffers x (Fx 32*FR + Fn 32*FR) = 34816 B -> 2 blocks/SM.
// ---------------------------------------------------------------------------
__device__ __forceinline__ void cp16(unsigned int saddr, const void* g) {
    asm volatile("cp.async.cg.shared.global [%0], [%1], 16;" :: "r"(saddr), "l"(g));
}

__global__ void __launch_bounds__(256, 2)
compute_mma() {
    __shared__ float Fbuf[2][2][32 * FR];     // [buf][x/n][rows]

    const int t = threadIdx.x;
    const int w = t >> 5, lane = t & 31;
    const int g = lane >> 2, t4 = lane & 3;
    const int wcol = w * 32;                  // global output col base
    const bool isN = (w >= 4);
    const float inv25 = 1.0f / 25.0f;

    // ---- load B fragments (weights) once: b[n8][k8][2] ----
    unsigned bfr[4][8][2];
#pragma unroll
    for (int n8 = 0; n8 < 4; n8++) {
        int c = wcol + n8 * 8 + g;
#pragma unroll
        for (int k8 = 0; k8 < 8; k8++) {
            float v0 = g_Atc[c * 64 + k8 * 8 + t4];
            float v1 = g_Atc[c * 64 + k8 * 8 + t4 + 4];
            CVT_TF32(bfr[n8][k8][0], v0);
            CVT_TF32(bfr[n8][k8][1], v1);
        }
    }
    float biasE[4], biasO[4];
#pragma unroll
    for (int n8 = 0; n8 < 4; n8++) {
        biasE[n8] = g_bias1[wcol + n8 * 8 + 2 * t4];
        biasO[n8] = g_bias1[wcol + n8 * 8 + 2 * t4 + 1];
    }
    const float x0v = (t < 128) ? g_x0[t] : 0.f;

    // staging helper indices: 400 float4 pairs over 256 threads
    // prefetch batch i into buffer b
#define STAGE(i_, b_)                                                         \
    do {                                                                      \
        const float4* src_ = (const float4*)(g_feats + (size_t)(i_) * NS * 128); \
        unsigned bx_ = (unsigned)__cvta_generic_to_shared(&Fbuf[b_][0][0]);   \
        unsigned bn_ = (unsigned)__cvta_generic_to_shared(&Fbuf[b_][1][0]);   \
        _Pragma("unroll")                                                     \
        for (int idx = t; idx < 400; idx += 256) {                            \
            int s_ = idx >> 4, q_ = idx & 15;                                 \
            cp16(bx_ + (s_ * FR + q_ * 4) * 4, src_ + s_ * 32 + q_);          \
            cp16(bn_ + (s_ * FR + q_ * 4) * 4, src_ + s_ * 32 + 16 + q_);     \
        }                                                                     \
        asm volatile("cp.async.commit_group;" ::: "memory");                  \
    } while (0)

    int i = blockIdx.x;
    if (i < BATCH) STAGE(i, 0);
    int buf = 0;

    for (; i < BATCH; i += CGRID) {
        const int nxt = i + CGRID;
        // all warps done reading buf^1 (previous iteration) -> safe to refill
        if (nxt < BATCH) {
            STAGE(nxt, buf ^ 1);
            asm volatile("cp.async.wait_group 1;" ::: "memory");
        } else {
            asm volatile("cp.async.wait_group 0;" ::: "memory");
        }
        __syncthreads();              // current buffer fully staged (all threads)

        float* Fx = &Fbuf[buf][0][0];
        float* Fn = &Fbuf[buf][1][0];
        if (t < 64) {                 // mean1 -> Fn row 25
            float m = 0.f;
#pragma unroll
            for (int s = 0; s < NS; s++) m += Fx[s * FR + t];
            Fn[25 * FR + t] = m * inv25;
        }
        __syncthreads();

        const float* Fw = isN ? Fn : Fx;

        // ---- mma ----
        float cfr[2][4][4];
#pragma unroll
        for (int m = 0; m < 2; m++)
#pragma unroll
            for (int n8 = 0; n8 < 4; n8++)
#pragma unroll
                for (int q = 0; q < 4; q++) cfr[m][n8][q] = 0.f;

#pragma unroll
        for (int m = 0; m < 2; m++) {
            int rb = m * 16;
#pragma unroll
            for (int k8 = 0; k8 < 8; k8++) {
                unsigned a0, a1, a2, a3;
                CVT_TF32(a0, Fw[(rb + g) * FR + k8 * 8 + t4]);
                CVT_TF32(a1, Fw[(rb + g + 8) * FR + k8 * 8 + t4]);
                CVT_TF32(a2, Fw[(rb + g) * FR + k8 * 8 + t4 + 4]);
                CVT_TF32(a3, Fw[(rb + g + 8) * FR + k8 * 8 + t4 + 4]);
#pragma unroll
                for (int n8 = 0; n8 < 4; n8++)
                    MMA_TF32(cfr[m][n8][0], cfr[m][n8][1], cfr[m][n8][2], cfr[m][n8][3],
                             a0, a1, a2, a3, bfr[n8][k8][0], bfr[n8][k8][1]);
            }
        }

        // ---- epilogue ----
        float* scr = g_scr + (size_t)i * 512;
        if (t < 128) scr[t] = fmaxf(x0v, 0.f);     // h0 x-part
#pragma unroll
        for (int n8 = 0; n8 < 4; n8++) {
            // rows: tile0 c0/c1 -> s=g, c2/c3 -> s=8+g; tile1 c0/c1 -> s=16+g
            // tile1 c2/c3 -> s=24+g (valid for sum only g==0; g==1 is mean1 row)
            float vE = fmaxf(cfr[0][n8][0] + biasE[n8], 0.f)
                     + fmaxf(cfr[0][n8][2] + biasE[n8], 0.f)
                     + fmaxf(cfr[1][n8][0] + biasE[n8], 0.f);
            float vO = fmaxf(cfr[0][n8][1] + biasO[n8], 0.f)
                     + fmaxf(cfr[0][n8][3] + biasO[n8], 0.f)
                     + fmaxf(cfr[1][n8][1] + biasO[n8], 0.f);
            if (g == 0) {
                vE += fmaxf(cfr[1][n8][2] + biasE[n8], 0.f);
                vO += fmaxf(cfr[1][n8][3] + biasO[n8], 0.f);
            }
            if (isN && g == 1) {       // row 25 = mean1 @ A1n -> h0 n-part
                scr[wcol + n8 * 8 + 2 * t4]     = fmaxf(cfr[1][n8][2] + biasE[n8], 0.f);
                scr[wcol + n8 * 8 + 2 * t4 + 1] = fmaxf(cfr[1][n8][3] + biasO[n8], 0.f);
            }
#pragma unroll
            for (int o = 4; o < 32; o <<= 1) {
                vE += __shfl_xor_sync(0xffffffffu, vE, o);
                vO += __shfl_xor_sync(0xffffffffu, vO, o);
            }
            if (lane < 4) {
                scr[256 + wcol + n8 * 8 + 2 * lane]     = vE * inv25;
                scr[256 + wcol + n8 * 8 + 2 * lane + 1] = vO * inv25;
            }
        }
        __syncthreads();              // everyone done with buf before next refill
        buf ^= 1;
    }
#undef STAGE
}

// ---------------------------------------------------------------------------
// final2: layer-2 GEMM with packed transposed weights (proven). 32 rows/blk.
// ---------------------------------------------------------------------------
__global__ void __launch_bounds__(256)
final2(const float* __restrict__ fcW,
       const float* __restrict__ fcb,
       float* __restrict__ out) {
    extern __shared__ float fsm[];
    float* in_sh = fsm;                 // 32 x 512
    float* sSq   = fsm + 32 * 512;
    float* sDot  = sSq + 32;

    int t  = threadIdx.x;
    int r0 = blockIdx.x * 32;

    {
        const float4* src = (const float4*)(g_scr + (size_t)r0 * 512);
        float4* dst = (float4*)in_sh;
#pragma unroll
        for (int q = 0; q < 16; q++) dst[t + q * 256] = src[t + q * 256];
    }
    if (t < 32) { sSq[t] = 0.f; sDot[t] = 0.f; }
    __syncthreads();

    const int c4 = (t & 63) * 4;
    const int rg = t >> 6;
    const int ioff = (c4 < 128) ? 0 : 256;
    const float* xb = in_sh + rg * 8 * 512 + ioff;

    ull acc[8][4];
#pragma unroll
    for (int r = 0; r < 8; r++)
#pragma unroll
        for (int j = 0; j < 4; j++) acc[r][j] = 0ull;

#pragma unroll 4
    for (int kp = 0; kp < 128; kp++) {
        ulonglong2 wA = *(const ulonglong2*)(g_W2t + kp * 512 + c4 * 2);
        ulonglong2 wB = *(const ulonglong2*)(g_W2t + kp * 512 + c4 * 2 + 4);
#pragma unroll
        for (int r = 0; r < 8; r++) {
            ull x2 = *(const ull*)(xb + r * 512 + 2 * kp);
            FFMA2(acc[r][0], x2, wA.x);
            FFMA2(acc[r][1], x2, wA.y);
            FFMA2(acc[r][2], x2, wB.x);
            FFMA2(acc[r][3], x2, wB.y);
        }
    }

    float4 fw = *(const float4*)(fcW + c4);
    int lane = t & 31;
#pragma unroll
    for (int r = 0; r < 8; r++) {
        float v[4];
#pragma unroll
        for (int j = 0; j < 4; j++)
            v[j] = __uint_as_float((unsigned)acc[r][j])
                 + __uint_as_float((unsigned)(acc[r][j] >> 32));
        float sq = v[0]*v[0] + v[1]*v[1] + v[2]*v[2] + v[3]*v[3];
        float dt = v[0]*fw.x + v[1]*fw.y + v[2]*fw.z + v[3]*fw.w;
#pragma unroll
        for (int o = 16; o > 0; o >>= 1) {
            sq += __shfl_xor_sync(0xffffffffu, sq, o);
            dt += __shfl_xor_sync(0xffffffffu, dt, o);
        }
        if (lane == 0) {
            atomicAdd(&sSq[rg * 8 + r], sq);
            atomicAdd(&sDot[rg * 8 + r], dt);
        }
    }
    __syncthreads();
    if (t < 32) {
        float nrm = sqrtf(sSq[t]);
        out[r0 + t] = sDot[t] / fmaxf(nrm, 1e-12f) + fcb[0];
    }
}

// ---------------------------------------------------------------------------
extern "C" void kernel_launch(void* const* d_in, const int* in_sizes, int n_in,
                              void* d_out, int out_size) {
    const float* embedding = (const float*)d_in[0];
    const float* prep_W    = (const float*)d_in[1];
    const float* prep_b    = (const float*)d_in[2];
    const float* w1x       = (const float*)d_in[3];
    const float* w1n       = (const float*)d_in[4];
    const float* w2x       = (const float*)d_in[5];
    const float* w2n       = (const float*)d_in[6];
    const float* fcW       = (const float*)d_in[7];
    const float* fcb       = (const float*)d_in[8];
    const int*   ids       = (const int*)d_in[9];
    const int*   adj       = (const int*)d_in[10];
    const int*   perm1     = (const int*)d_in[11];
    const int*   perm2     = (const int*)d_in[12];
    const int n_nodes = in_sizes[0] / EMB - 1;

    prep_A<<<64, 128>>>(prep_W, w1x, w1n);
    prep_B<<<1, 128>>>(embedding, prep_W, prep_b, w1x, w1n, n_nodes);
    prep_W2<<<512, 256>>>(w2x, w2n);

    gather_kernel<<<NSAMP / 8, 256>>>(embedding, ids, adj, perm1, perm2);

    compute_mma<<<CGRID, 256>>>();

    const int smem_o = (32 * 512 + 64) * (int)sizeof(float);
    cudaFuncSetAttribute(final2, cudaFuncAttributeMaxDynamicSharedMemorySize, smem_o);
    final2<<<BATCH / 32, 256, smem_o>>>(fcW, fcb, (float*)d_out);
}